// round 12
// baseline (speedup 1.0000x reference)
#include <cuda_runtime.h>
#include <cuda_fp16.h>
#include <math.h>
#include <stdint.h>

#define NN 50000
#define NE 600000
#define FEATS 128

#define SCAN_CHUNK 1024
#define NCHUNK ((NN + SCAN_CHUNK - 1) / SCAN_CHUNK)   // 49

// -------------------- device scratch ---------------------------------------
__device__ __align__(128) int g_idx64;
__device__ int g_count[NN];
__device__ int g_off[NN + 1];
__device__ int g_cursor[NN];
__device__ __align__(128) unsigned long long g_btot64[64];
__device__ int g_edges[NE];
__device__ float g_agg[NN * FEATS];
__device__ __half g_feath[NN * FEATS];   // fp16 copy of feature

__device__ __forceinline__ int load_idx(const void* p, int i) {
    return g_idx64 ? (int)((const long long*)p)[i] : ((const int*)p)[i];
}

// ======================= feat -> fp16 conversion (runs on stream 2) =========
__global__ __launch_bounds__(256) void convert_kernel(
    const float* __restrict__ feat, int nNodes) {
    int i = blockIdx.x * 256 + threadIdx.x;   // one thread = 8 floats
    if (i >= nNodes * (FEATS / 8)) return;
    const float4* src = (const float4*)feat + i * 2;
    float4 a = __ldg(src);
    float4 b = __ldg(src + 1);
    half2 h0 = __float22half2_rn(make_float2(a.x, a.y));
    half2 h1 = __float22half2_rn(make_float2(a.z, a.w));
    half2 h2 = __float22half2_rn(make_float2(b.x, b.y));
    half2 h3 = __float22half2_rn(make_float2(b.z, b.w));
    uint4 o;
    o.x = *(uint32_t*)&h0; o.y = *(uint32_t*)&h1;
    o.z = *(uint32_t*)&h2; o.w = *(uint32_t*)&h3;
    *(uint4*)(g_feath + (long)i * 8) = o;
}

// ======================= CSR build: 4 small kernels =========================
__global__ void init_kernel(const void* __restrict__ src) {
    int i = blockIdx.x * blockDim.x + threadIdx.x;
    if (i < NN) g_count[i] = 0;
    if (blockIdx.x == 0 && threadIdx.x == 0) {
        const long long* p = (const long long*)src;
        int is64 = 1;
        for (int k = 0; k < 64; k++) {
            long long v = p[k];
            if (v < 0 || v >= NN) { is64 = 0; break; }
        }
        g_idx64 = is64;
    }
}

__global__ void hist_kernel(const void* __restrict__ dst, int nE) {
    int i = (blockIdx.x * blockDim.x + threadIdx.x) * 2;
    if (g_idx64) {
        const long long* p = (const long long*)dst;
        if (i + 1 < nE) {
            longlong2 v = *(const longlong2*)(p + i);
            atomicAdd(&g_count[(int)v.x], 1);
            atomicAdd(&g_count[(int)v.y], 1);
        } else if (i < nE) {
            atomicAdd(&g_count[(int)p[i]], 1);
        }
    } else {
        const int* p = (const int*)dst;
        if (i + 1 < nE) {
            int2 v = *(const int2*)(p + i);
            atomicAdd(&g_count[v.x], 1);
            atomicAdd(&g_count[v.y], 1);
        } else if (i < nE) {
            atomicAdd(&g_count[p[i]], 1);
        }
    }
}

// merged scan: chunk scan + self-tagged decoupled lookback (replay-safe)
__global__ __launch_bounds__(SCAN_CHUNK) void scan_kernel(int nE) {
    __shared__ int wsum[32];
    __shared__ long long stot[64];
    __shared__ unsigned mytag_s;

    int tid = threadIdx.x;
    int bid = blockIdx.x;
    int lane = tid & 31, wid = tid >> 5;

    if (tid == 0) {
        unsigned long long old = *(volatile unsigned long long*)&g_btot64[bid];
        mytag_s = (unsigned)(old >> 32) + 1;   // per-slot pass tag
    }

    int gid = bid * SCAN_CHUNK + tid;
    int v = (gid < NN) ? g_count[gid] : 0;
    int x = v;
    #pragma unroll
    for (int o = 1; o < 32; o <<= 1) {
        int y = __shfl_up_sync(0xffffffff, x, o);
        if (lane >= o) x += y;
    }
    if (lane == 31) wsum[wid] = x;
    __syncthreads();   // also publishes mytag_s
    if (wid == 0) {
        int s = wsum[lane];
        #pragma unroll
        for (int o = 1; o < 32; o <<= 1) {
            int y = __shfl_up_sync(0xffffffff, s, o);
            if (lane >= o) s += y;
        }
        wsum[lane] = s;
    }
    __syncthreads();
    int pre = (wid > 0) ? wsum[wid - 1] : 0;
    int incl = x + pre;
    int excl = incl - v;
    unsigned mytag = mytag_s;

    // publish my chunk total with bumped tag
    if (tid == SCAN_CHUNK - 1) {
        unsigned long long val = ((unsigned long long)mytag << 32) | (unsigned)incl;
        *(volatile unsigned long long*)&g_btot64[bid] = val;
        __threadfence();
    }
    // lookback: spin-read all predecessors in parallel
    if (tid < 64) {
        long long t = 0;
        if (tid < bid) {
            unsigned long long v64;
            do {
                v64 = *(volatile unsigned long long*)&g_btot64[tid];
            } while ((unsigned)(v64 >> 32) != mytag);
            t = (long long)(v64 & 0xffffffffULL);
        }
        stot[tid] = t;
    }
    __syncthreads();
    if (tid < 32) {
        long long s = stot[tid] + stot[tid + 32];
        #pragma unroll
        for (int o = 16; o > 0; o >>= 1)
            s += __shfl_down_sync(0xffffffff, s, o);
        if (tid == 0) stot[0] = s;
    }
    __syncthreads();
    int add = (int)stot[0];

    if (gid < NN) {
        int o = excl + add;
        g_off[gid] = o;
        g_cursor[gid] = o;
    }
    if (bid == 0 && tid == 0) g_off[NN] = nE;
}

__global__ void fill_kernel(const void* __restrict__ src,
                            const void* __restrict__ dst, int nE) {
    int i = (blockIdx.x * blockDim.x + threadIdx.x) * 2;
    #pragma unroll
    for (int u = 0; u < 2; u++) {
        int j = i + u;
        if (j < nE) {
            int d = load_idx(dst, j);
            int s = load_idx(src, j);
            int pos = atomicAdd(&g_cursor[d], 1);
            g_edges[pos] = s;
        }
    }
}

// ======================= gather (fp16 table, fp32 accumulate) ===============
__global__ __launch_bounds__(256) void gather_kernel(int nNodes) {
    int node = (blockIdx.x * 256 + threadIdx.x) >> 5;
    if (node >= nNodes) return;
    int l4 = (threadIdx.x & 31) * 4;
    int eb = __ldg(&g_off[node]);
    int ee = __ldg(&g_off[node + 1]);
    float4 acc = make_float4(0.f, 0.f, 0.f, 0.f);
    for (int e = eb; e < ee; e += 8) {
        #pragma unroll
        for (int u = 0; u < 8; u++) {
            int j = e + u;
            int s = g_edges[j < ee ? j : eb];
            uint2 raw = *(const uint2*)(g_feath + (long)s * FEATS + l4);
            half2 h0 = *(half2*)&raw.x;
            half2 h1 = *(half2*)&raw.y;
            float2 f0 = __half22float2(h0);
            float2 f1 = __half22float2(h1);
            if (j < ee) {
                acc.x += f0.x; acc.y += f0.y;
                acc.z += f1.x; acc.w += f1.y;
            }
        }
    }
    *(float4*)(g_agg + (long)node * FEATS + l4) = acc;
}

// ======================= GEMM via mma.sync bf16 split (proven) ==============
#define GSTR 136
#define SM_WH 0
#define SM_WL (SM_WH + 128 * GSTR * 2)
#define SM_AH (SM_WL + 128 * GSTR * 2)
#define SM_AL (SM_AH + 64 * GSTR * 2)
#define GEMM_SMEM (SM_AL + 64 * GSTR * 2)

#define MMA_BF16(c0, c1, c2, c3, a0, a1, a2, a3, b0, b1)                      \
    asm volatile(                                                             \
        "mma.sync.aligned.m16n8k16.row.col.f32.bf16.bf16.f32 "                \
        "{%0,%1,%2,%3}, {%4,%5,%6,%7}, {%8,%9}, {%0,%1,%2,%3};"               \
        : "+f"(c0), "+f"(c1), "+f"(c2), "+f"(c3)                              \
        : "r"(a0), "r"(a1), "r"(a2), "r"(a3), "r"(b0), "r"(b1))

__device__ __forceinline__ uint32_t pack_bf16(float lo, float hi) {
    uint32_t r;
    asm("cvt.rn.bf16x2.f32 %0, %1, %2;" : "=r"(r) : "f"(hi), "f"(lo));
    return r;
}

__device__ __forceinline__ void split4(float4 a, uint2& h, uint2& l) {
    uint32_t h01 = pack_bf16(a.x, a.y);
    uint32_t h23 = pack_bf16(a.z, a.w);
    float r0 = a.x - __uint_as_float(h01 << 16);
    float r1 = a.y - __uint_as_float(h01 & 0xffff0000u);
    float r2 = a.z - __uint_as_float(h23 << 16);
    float r3 = a.w - __uint_as_float(h23 & 0xffff0000u);
    h = make_uint2(h01, h23);
    l = make_uint2(pack_bf16(r0, r1), pack_bf16(r2, r3));
}

__global__ __launch_bounds__(256, 2) void gemm_mma_kernel(
    const float* __restrict__ W, const float* __restrict__ b,
    float* __restrict__ out, int nNodes) {
    extern __shared__ char sm[];
    uint16_t* WH = (uint16_t*)(sm + SM_WH);
    uint16_t* WL = (uint16_t*)(sm + SM_WL);
    uint16_t* AH = (uint16_t*)(sm + SM_AH);
    uint16_t* AL = (uint16_t*)(sm + SM_AL);

    int tid = threadIdx.x;
    int lane = tid & 31;
    int warp = tid >> 5;
    int g = lane >> 2;
    int t = lane & 3;
    int mbase = (warp & 3) * 16;
    int nbase = (warp >> 2) * 64;

    for (int i = tid; i < 128 * 32; i += 256) {
        int j = i >> 5;
        int k4 = (i & 31) << 2;
        float4 w = __ldg((const float4*)(W + j * 128 + k4));
        uint2 h, l;
        split4(w, h, l);
        *(uint2*)(WH + j * GSTR + k4) = h;
        *(uint2*)(WL + j * GSTR + k4) = l;
    }

    float2 bv[8];
    #pragma unroll
    for (int nc = 0; nc < 8; nc++)
        bv[nc] = *(const float2*)(b + nbase + nc * 8 + t * 2);

    for (int tile = blockIdx.x * 64; tile < nNodes; tile += gridDim.x * 64) {
        __syncthreads();

        for (int i = tid; i < 64 * 32; i += 256) {
            int r = i >> 5;
            int k4 = (i & 31) << 2;
            int row = tile + r;
            if (row >= nNodes) row = nNodes - 1;
            float4 a = *(const float4*)(g_agg + (long)row * 128 + k4);
            uint2 h, l;
            split4(a, h, l);
            *(uint2*)(AH + r * GSTR + k4) = h;
            *(uint2*)(AL + r * GSTR + k4) = l;
        }
        __syncthreads();

        float c[8][4];
        #pragma unroll
        for (int nc = 0; nc < 8; nc++)
            #pragma unroll
            for (int i = 0; i < 4; i++) c[nc][i] = 0.f;

        #pragma unroll 1
        for (int kc = 0; kc < 8; kc++) {
            int k0 = kc * 16;
            const uint16_t* arh = AH + (mbase + g) * GSTR + k0;
            const uint16_t* arl = AL + (mbase + g) * GSTR + k0;
            uint32_t ah0 = *(const uint32_t*)(arh + t * 2);
            uint32_t ah1 = *(const uint32_t*)(arh + 8 * GSTR + t * 2);
            uint32_t ah2 = *(const uint32_t*)(arh + t * 2 + 8);
            uint32_t ah3 = *(const uint32_t*)(arh + 8 * GSTR + t * 2 + 8);
            uint32_t al0 = *(const uint32_t*)(arl + t * 2);
            uint32_t al1 = *(const uint32_t*)(arl + 8 * GSTR + t * 2);
            uint32_t al2 = *(const uint32_t*)(arl + t * 2 + 8);
            uint32_t al3 = *(const uint32_t*)(arl + 8 * GSTR + t * 2 + 8);

            #pragma unroll
            for (int nc = 0; nc < 8; nc++) {
                int j = nbase + nc * 8 + g;
                uint32_t bh0 = *(const uint32_t*)(WH + j * GSTR + k0 + t * 2);
                uint32_t bh1 = *(const uint32_t*)(WH + j * GSTR + k0 + t * 2 + 8);
                uint32_t bl0 = *(const uint32_t*)(WL + j * GSTR + k0 + t * 2);
                uint32_t bl1 = *(const uint32_t*)(WL + j * GSTR + k0 + t * 2 + 8);
                MMA_BF16(c[nc][0], c[nc][1], c[nc][2], c[nc][3],
                         ah0, ah1, ah2, ah3, bh0, bh1);
                MMA_BF16(c[nc][0], c[nc][1], c[nc][2], c[nc][3],
                         ah0, ah1, ah2, ah3, bl0, bl1);
                MMA_BF16(c[nc][0], c[nc][1], c[nc][2], c[nc][3],
                         al0, al1, al2, al3, bh0, bh1);
            }
        }

        int row0 = tile + mbase + g;
        int row1 = row0 + 8;
        #pragma unroll
        for (int nc = 0; nc < 8; nc++) {
            int n0 = nbase + nc * 8 + t * 2;
            if (row0 < nNodes) {
                float2 o0;
                o0.x = tanhf(c[nc][0] + bv[nc].x);
                o0.y = tanhf(c[nc][1] + bv[nc].y);
                *(float2*)(out + (long)row0 * 128 + n0) = o0;
            }
            if (row1 < nNodes) {
                float2 o1;
                o1.x = tanhf(c[nc][2] + bv[nc].x);
                o1.y = tanhf(c[nc][3] + bv[nc].y);
                *(float2*)(out + (long)row1 * 128 + n0) = o1;
            }
        }
    }
}

// ---------------------------------------------------------------------------
extern "C" void kernel_launch(void* const* d_in, const int* in_sizes, int n_in,
                              void* d_out, int out_size) {
    const float* feature = (const float*)d_in[0];
    const float* W       = (const float*)d_in[1];
    const float* b       = (const float*)d_in[2];
    const void*  src     = d_in[3];
    const void*  dst     = d_in[4];
    float* out = (float*)d_out;

    int nEdges = in_sizes[3];
    int nNodes = out_size / FEATS;

    static cudaStream_t s2 = nullptr;
    static cudaEvent_t eFork = nullptr, eJoin = nullptr;
    if (!s2) {
        cudaStreamCreateWithFlags(&s2, cudaStreamNonBlocking);
        cudaEventCreateWithFlags(&eFork, cudaEventDisableTiming);
        cudaEventCreateWithFlags(&eJoin, cudaEventDisableTiming);
        cudaFuncSetAttribute(gemm_mma_kernel,
                             cudaFuncAttributeMaxDynamicSharedMemorySize, GEMM_SMEM);
    }

    // fork: fp16 conversion overlaps the CSR build
    cudaEventRecord(eFork, 0);
    cudaStreamWaitEvent(s2, eFork, 0);
    convert_kernel<<<(nNodes * (FEATS / 8) + 255) / 256, 256, 0, s2>>>(feature, nNodes);
    cudaEventRecord(eJoin, s2);

    init_kernel<<<(NN + 511) / 512, 512>>>(src);
    hist_kernel<<<(nEdges / 2 + 511) / 512, 512>>>(dst, nEdges);
    scan_kernel<<<NCHUNK, SCAN_CHUNK>>>(nEdges);
    fill_kernel<<<(nEdges / 2 + 511) / 512, 512>>>(src, dst, nEdges);

    cudaStreamWaitEvent(0, eJoin, 0);
    gather_kernel<<<(nNodes * 32 + 255) / 256, 256>>>(nNodes);

    gemm_mma_kernel<<<296, 256, GEMM_SMEM>>>(W, b, out, nNodes);
}

// round 13
// speedup vs baseline: 1.1109x; 1.1109x over previous
#include <cuda_runtime.h>
#include <math.h>
#include <stdint.h>

#define NN 50000
#define NE 600000
#define FEATS 128

#define SCAN_CHUNK 1024
#define NCHUNK ((NN + SCAN_CHUNK - 1) / SCAN_CHUNK)   // 49

// -------------------- device scratch ---------------------------------------
__device__ __align__(128) int g_idx64;
__device__ int g_count[NN];
__device__ int g_off[NN + 1];
__device__ int g_cursor[NN];
__device__ __align__(128) unsigned long long g_btot64[64];
__device__ int g_edges[NE];
__device__ float g_fx[NN * FEATS];   // feat @ W^T

__device__ __forceinline__ int load_idx(const void* p, int i) {
    return g_idx64 ? (int)((const long long*)p)[i] : ((const int*)p)[i];
}

// ======================= CSR build: 4 small kernels =========================
__global__ void init_kernel(const void* __restrict__ src) {
    int i = blockIdx.x * blockDim.x + threadIdx.x;
    if (i < NN) g_count[i] = 0;
    if (blockIdx.x == 0 && threadIdx.x == 0) {
        const long long* p = (const long long*)src;
        int is64 = 1;
        for (int k = 0; k < 64; k++) {
            long long v = p[k];
            if (v < 0 || v >= NN) { is64 = 0; break; }
        }
        g_idx64 = is64;
    }
}

__global__ void hist_kernel(const void* __restrict__ dst, int nE) {
    int i = (blockIdx.x * blockDim.x + threadIdx.x) * 2;
    if (g_idx64) {
        const long long* p = (const long long*)dst;
        if (i + 1 < nE) {
            longlong2 v = *(const longlong2*)(p + i);
            atomicAdd(&g_count[(int)v.x], 1);
            atomicAdd(&g_count[(int)v.y], 1);
        } else if (i < nE) {
            atomicAdd(&g_count[(int)p[i]], 1);
        }
    } else {
        const int* p = (const int*)dst;
        if (i + 1 < nE) {
            int2 v = *(const int2*)(p + i);
            atomicAdd(&g_count[v.x], 1);
            atomicAdd(&g_count[v.y], 1);
        } else if (i < nE) {
            atomicAdd(&g_count[p[i]], 1);
        }
    }
}

// merged scan: chunk scan + self-tagged decoupled lookback (replay-safe, R12-proven)
__global__ __launch_bounds__(SCAN_CHUNK) void scan_kernel(int nE) {
    __shared__ int wsum[32];
    __shared__ long long stot[64];
    __shared__ unsigned mytag_s;

    int tid = threadIdx.x;
    int bid = blockIdx.x;
    int lane = tid & 31, wid = tid >> 5;

    if (tid == 0) {
        unsigned long long old = *(volatile unsigned long long*)&g_btot64[bid];
        mytag_s = (unsigned)(old >> 32) + 1;
    }

    int gid = bid * SCAN_CHUNK + tid;
    int v = (gid < NN) ? g_count[gid] : 0;
    int x = v;
    #pragma unroll
    for (int o = 1; o < 32; o <<= 1) {
        int y = __shfl_up_sync(0xffffffff, x, o);
        if (lane >= o) x += y;
    }
    if (lane == 31) wsum[wid] = x;
    __syncthreads();
    if (wid == 0) {
        int s = wsum[lane];
        #pragma unroll
        for (int o = 1; o < 32; o <<= 1) {
            int y = __shfl_up_sync(0xffffffff, s, o);
            if (lane >= o) s += y;
        }
        wsum[lane] = s;
    }
    __syncthreads();
    int pre = (wid > 0) ? wsum[wid - 1] : 0;
    int incl = x + pre;
    int excl = incl - v;
    unsigned mytag = mytag_s;

    if (tid == SCAN_CHUNK - 1) {
        unsigned long long val = ((unsigned long long)mytag << 32) | (unsigned)incl;
        *(volatile unsigned long long*)&g_btot64[bid] = val;
        __threadfence();
    }
    if (tid < 64) {
        long long t = 0;
        if (tid < bid) {
            unsigned long long v64;
            do {
                v64 = *(volatile unsigned long long*)&g_btot64[tid];
            } while ((unsigned)(v64 >> 32) != mytag);
            t = (long long)(v64 & 0xffffffffULL);
        }
        stot[tid] = t;
    }
    __syncthreads();
    if (tid < 32) {
        long long s = stot[tid] + stot[tid + 32];
        #pragma unroll
        for (int o = 16; o > 0; o >>= 1)
            s += __shfl_down_sync(0xffffffff, s, o);
        if (tid == 0) stot[0] = s;
    }
    __syncthreads();
    int add = (int)stot[0];

    if (gid < NN) {
        int o = excl + add;
        g_off[gid] = o;
        g_cursor[gid] = o;
    }
    if (bid == 0 && tid == 0) g_off[NN] = nE;
}

__global__ void fill_kernel(const void* __restrict__ src,
                            const void* __restrict__ dst, int nE) {
    int i = (blockIdx.x * blockDim.x + threadIdx.x) * 2;
    #pragma unroll
    for (int u = 0; u < 2; u++) {
        int j = i + u;
        if (j < nE) {
            int d = load_idx(dst, j);
            int s = load_idx(src, j);
            int pos = atomicAdd(&g_cursor[d], 1);
            g_edges[pos] = s;
        }
    }
}

// ======================= GEMM via mma.sync bf16 split: fx = feat @ W^T ======
#define GSTR 136
#define SM_WH 0
#define SM_WL (SM_WH + 128 * GSTR * 2)
#define SM_AH (SM_WL + 128 * GSTR * 2)
#define SM_AL (SM_AH + 64 * GSTR * 2)
#define GEMM_SMEM (SM_AL + 64 * GSTR * 2)

#define MMA_BF16(c0, c1, c2, c3, a0, a1, a2, a3, b0, b1)                      \
    asm volatile(                                                             \
        "mma.sync.aligned.m16n8k16.row.col.f32.bf16.bf16.f32 "                \
        "{%0,%1,%2,%3}, {%4,%5,%6,%7}, {%8,%9}, {%0,%1,%2,%3};"               \
        : "+f"(c0), "+f"(c1), "+f"(c2), "+f"(c3)                              \
        : "r"(a0), "r"(a1), "r"(a2), "r"(a3), "r"(b0), "r"(b1))

__device__ __forceinline__ uint32_t pack_bf16(float lo, float hi) {
    uint32_t r;
    asm("cvt.rn.bf16x2.f32 %0, %1, %2;" : "=r"(r) : "f"(hi), "f"(lo));
    return r;
}

__device__ __forceinline__ void split4(float4 a, uint2& h, uint2& l) {
    uint32_t h01 = pack_bf16(a.x, a.y);
    uint32_t h23 = pack_bf16(a.z, a.w);
    float r0 = a.x - __uint_as_float(h01 << 16);
    float r1 = a.y - __uint_as_float(h01 & 0xffff0000u);
    float r2 = a.z - __uint_as_float(h23 << 16);
    float r3 = a.w - __uint_as_float(h23 & 0xffff0000u);
    h = make_uint2(h01, h23);
    l = make_uint2(pack_bf16(r0, r1), pack_bf16(r2, r3));
}

__global__ __launch_bounds__(256, 2) void gemm_mma_kernel(
    const float* __restrict__ feat, const float* __restrict__ W, int nNodes) {
    extern __shared__ char sm[];
    uint16_t* WH = (uint16_t*)(sm + SM_WH);
    uint16_t* WL = (uint16_t*)(sm + SM_WL);
    uint16_t* AH = (uint16_t*)(sm + SM_AH);
    uint16_t* AL = (uint16_t*)(sm + SM_AL);

    int tid = threadIdx.x;
    int lane = tid & 31;
    int warp = tid >> 5;
    int g = lane >> 2;
    int t = lane & 3;
    int mbase = (warp & 3) * 16;
    int nbase = (warp >> 2) * 64;

    for (int i = tid; i < 128 * 32; i += 256) {
        int j = i >> 5;
        int k4 = (i & 31) << 2;
        float4 w = __ldg((const float4*)(W + j * 128 + k4));
        uint2 h, l;
        split4(w, h, l);
        *(uint2*)(WH + j * GSTR + k4) = h;
        *(uint2*)(WL + j * GSTR + k4) = l;
    }

    for (int tile = blockIdx.x * 64; tile < nNodes; tile += gridDim.x * 64) {
        __syncthreads();

        for (int i = tid; i < 64 * 32; i += 256) {
            int r = i >> 5;
            int k4 = (i & 31) << 2;
            int row = tile + r;
            if (row >= nNodes) row = nNodes - 1;
            float4 a = __ldg((const float4*)(feat + (long)row * 128 + k4));
            uint2 h, l;
            split4(a, h, l);
            *(uint2*)(AH + r * GSTR + k4) = h;
            *(uint2*)(AL + r * GSTR + k4) = l;
        }
        __syncthreads();

        float c[8][4];
        #pragma unroll
        for (int nc = 0; nc < 8; nc++)
            #pragma unroll
            for (int i = 0; i < 4; i++) c[nc][i] = 0.f;

        #pragma unroll 1
        for (int kc = 0; kc < 8; kc++) {
            int k0 = kc * 16;
            const uint16_t* arh = AH + (mbase + g) * GSTR + k0;
            const uint16_t* arl = AL + (mbase + g) * GSTR + k0;
            uint32_t ah0 = *(const uint32_t*)(arh + t * 2);
            uint32_t ah1 = *(const uint32_t*)(arh + 8 * GSTR + t * 2);
            uint32_t ah2 = *(const uint32_t*)(arh + t * 2 + 8);
            uint32_t ah3 = *(const uint32_t*)(arh + 8 * GSTR + t * 2 + 8);
            uint32_t al0 = *(const uint32_t*)(arl + t * 2);
            uint32_t al1 = *(const uint32_t*)(arl + 8 * GSTR + t * 2);
            uint32_t al2 = *(const uint32_t*)(arl + t * 2 + 8);
            uint32_t al3 = *(const uint32_t*)(arl + 8 * GSTR + t * 2 + 8);

            #pragma unroll
            for (int nc = 0; nc < 8; nc++) {
                int j = nbase + nc * 8 + g;
                uint32_t bh0 = *(const uint32_t*)(WH + j * GSTR + k0 + t * 2);
                uint32_t bh1 = *(const uint32_t*)(WH + j * GSTR + k0 + t * 2 + 8);
                uint32_t bl0 = *(const uint32_t*)(WL + j * GSTR + k0 + t * 2);
                uint32_t bl1 = *(const uint32_t*)(WL + j * GSTR + k0 + t * 2 + 8);
                MMA_BF16(c[nc][0], c[nc][1], c[nc][2], c[nc][3],
                         ah0, ah1, ah2, ah3, bh0, bh1);
                MMA_BF16(c[nc][0], c[nc][1], c[nc][2], c[nc][3],
                         ah0, ah1, ah2, ah3, bl0, bl1);
                MMA_BF16(c[nc][0], c[nc][1], c[nc][2], c[nc][3],
                         al0, al1, al2, al3, bh0, bh1);
            }
        }

        int row0 = tile + mbase + g;
        int row1 = row0 + 8;
        #pragma unroll
        for (int nc = 0; nc < 8; nc++) {
            int n0 = nbase + nc * 8 + t * 2;
            if (row0 < nNodes)
                *(float2*)(g_fx + (long)row0 * 128 + n0) =
                    make_float2(c[nc][0], c[nc][1]);
            if (row1 < nNodes)
                *(float2*)(g_fx + (long)row1 * 128 + n0) =
                    make_float2(c[nc][2], c[nc][3]);
        }
    }
}

// ======================= gather + bias + tanh (fp32, proven shape) ==========
__global__ __launch_bounds__(256) void gather_tanh_kernel(
    const float* __restrict__ b, float* __restrict__ out, int nNodes) {
    int node = (blockIdx.x * 256 + threadIdx.x) >> 5;
    if (node >= nNodes) return;
    int l4 = (threadIdx.x & 31) * 4;
    float4 bv = *(const float4*)(b + l4);
    int eb = __ldg(&g_off[node]);
    int ee = __ldg(&g_off[node + 1]);
    float4 acc = make_float4(0.f, 0.f, 0.f, 0.f);
    for (int e = eb; e < ee; e += 8) {
        #pragma unroll
        for (int u = 0; u < 8; u++) {
            int j = e + u;
            int s = g_edges[j < ee ? j : eb];
            float4 f = *(const float4*)(g_fx + (long)s * FEATS + l4);
            if (j < ee) {
                acc.x += f.x; acc.y += f.y;
                acc.z += f.z; acc.w += f.w;
            }
        }
    }
    float4 o;
    o.x = tanhf(acc.x + bv.x);
    o.y = tanhf(acc.y + bv.y);
    o.z = tanhf(acc.z + bv.z);
    o.w = tanhf(acc.w + bv.w);
    *(float4*)(out + (long)node * FEATS + l4) = o;
}

// ---------------------------------------------------------------------------
extern "C" void kernel_launch(void* const* d_in, const int* in_sizes, int n_in,
                              void* d_out, int out_size) {
    const float* feature = (const float*)d_in[0];
    const float* W       = (const float*)d_in[1];
    const float* b       = (const float*)d_in[2];
    const void*  src     = d_in[3];
    const void*  dst     = d_in[4];
    float* out = (float*)d_out;

    int nEdges = in_sizes[3];
    int nNodes = out_size / FEATS;

    static cudaStream_t s2 = nullptr;
    static cudaEvent_t eFork = nullptr, eJoin = nullptr;
    if (!s2) {
        cudaStreamCreateWithFlags(&s2, cudaStreamNonBlocking);
        cudaEventCreateWithFlags(&eFork, cudaEventDisableTiming);
        cudaEventCreateWithFlags(&eJoin, cudaEventDisableTiming);
        cudaFuncSetAttribute(gemm_mma_kernel,
                             cudaFuncAttributeMaxDynamicSharedMemorySize, GEMM_SMEM);
    }

    // fork: mma GEMM (feat @ W^T) on s2 overlaps the CSR build on stream 0
    cudaEventRecord(eFork, 0);
    cudaStreamWaitEvent(s2, eFork, 0);
    gemm_mma_kernel<<<296, 256, GEMM_SMEM, s2>>>(feature, W, nNodes);
    cudaEventRecord(eJoin, s2);

    init_kernel<<<(NN + 511) / 512, 512>>>(src);
    hist_kernel<<<(nEdges / 2 + 511) / 512, 512>>>(dst, nEdges);
    scan_kernel<<<NCHUNK, SCAN_CHUNK>>>(nEdges);
    fill_kernel<<<(nEdges / 2 + 511) / 512, 512>>>(src, dst, nEdges);

    // join, then gather + bias + tanh
    cudaStreamWaitEvent(0, eJoin, 0);
    gather_tanh_kernel<<<(nNodes * 32 + 255) / 256, 256>>>(b, out, nNodes);
}

// round 14
// speedup vs baseline: 1.2159x; 1.0946x over previous
#include <cuda_runtime.h>
#include <math.h>
#include <stdint.h>

#define NN 50000
#define NE 600000
#define FEATS 128
#define CAP 96   // slots per node; Poisson(12) => P(deg>96) ~ 1e-50

// -------------------- device scratch ---------------------------------------
__device__ __align__(128) int g_idx64;
__device__ __align__(128) int g_ocnt;
__device__ int g_cursor[NN];
__device__ int g_slots[NN * CAP];
__device__ int2 g_over[NE];          // overflow (d, s) pairs — normally empty
__device__ float g_fx[NN * FEATS];   // feat @ W^T

// ======================= init: zero cursors + overflow cnt + detect =========
__global__ void init_kernel(const void* __restrict__ src) {
    int i = blockIdx.x * blockDim.x + threadIdx.x;
    if (i < NN) g_cursor[i] = 0;
    if (blockIdx.x == 0 && threadIdx.x == 0) {
        g_ocnt = 0;
        const long long* p = (const long long*)src;
        int is64 = 1;
        for (int k = 0; k < 64; k++) {
            long long v = p[k];
            if (v < 0 || v >= NN) { is64 = 0; break; }
        }
        g_idx64 = is64;
    }
}

// ======================= fill: slot bucketing, no hist/scan ==================
__device__ __forceinline__ void fill_one(int d, int s) {
    int pos = atomicAdd(&g_cursor[d], 1);
    if (pos < CAP) {
        g_slots[d * CAP + pos] = s;
    } else {
        int o = atomicAdd(&g_ocnt, 1);
        g_over[o] = make_int2(d, s);
    }
}

__global__ void fill_kernel(const void* __restrict__ src,
                            const void* __restrict__ dst, int nE) {
    int i = (blockIdx.x * blockDim.x + threadIdx.x) * 2;
    if (g_idx64) {
        const long long* ps = (const long long*)src;
        const long long* pd = (const long long*)dst;
        if (i + 1 < nE) {
            longlong2 d2 = *(const longlong2*)(pd + i);
            longlong2 s2 = *(const longlong2*)(ps + i);
            fill_one((int)d2.x, (int)s2.x);
            fill_one((int)d2.y, (int)s2.y);
        } else if (i < nE) {
            fill_one((int)pd[i], (int)ps[i]);
        }
    } else {
        const int* ps = (const int*)src;
        const int* pd = (const int*)dst;
        if (i + 1 < nE) {
            int2 d2 = *(const int2*)(pd + i);
            int2 s2 = *(const int2*)(ps + i);
            fill_one(d2.x, s2.x);
            fill_one(d2.y, s2.y);
        } else if (i < nE) {
            fill_one(pd[i], ps[i]);
        }
    }
}

// ======================= GEMM via mma.sync bf16 split: fx = feat @ W^T ======
#define GSTR 136
#define SM_WH 0
#define SM_WL (SM_WH + 128 * GSTR * 2)
#define SM_AH (SM_WL + 128 * GSTR * 2)
#define SM_AL (SM_AH + 64 * GSTR * 2)
#define GEMM_SMEM (SM_AL + 64 * GSTR * 2)

#define MMA_BF16(c0, c1, c2, c3, a0, a1, a2, a3, b0, b1)                      \
    asm volatile(                                                             \
        "mma.sync.aligned.m16n8k16.row.col.f32.bf16.bf16.f32 "                \
        "{%0,%1,%2,%3}, {%4,%5,%6,%7}, {%8,%9}, {%0,%1,%2,%3};"               \
        : "+f"(c0), "+f"(c1), "+f"(c2), "+f"(c3)                              \
        : "r"(a0), "r"(a1), "r"(a2), "r"(a3), "r"(b0), "r"(b1))

__device__ __forceinline__ uint32_t pack_bf16(float lo, float hi) {
    uint32_t r;
    asm("cvt.rn.bf16x2.f32 %0, %1, %2;" : "=r"(r) : "f"(hi), "f"(lo));
    return r;
}

__device__ __forceinline__ void split4(float4 a, uint2& h, uint2& l) {
    uint32_t h01 = pack_bf16(a.x, a.y);
    uint32_t h23 = pack_bf16(a.z, a.w);
    float r0 = a.x - __uint_as_float(h01 << 16);
    float r1 = a.y - __uint_as_float(h01 & 0xffff0000u);
    float r2 = a.z - __uint_as_float(h23 << 16);
    float r3 = a.w - __uint_as_float(h23 & 0xffff0000u);
    h = make_uint2(h01, h23);
    l = make_uint2(pack_bf16(r0, r1), pack_bf16(r2, r3));
}

__global__ __launch_bounds__(256, 2) void gemm_mma_kernel(
    const float* __restrict__ feat, const float* __restrict__ W, int nNodes) {
    extern __shared__ char sm[];
    uint16_t* WH = (uint16_t*)(sm + SM_WH);
    uint16_t* WL = (uint16_t*)(sm + SM_WL);
    uint16_t* AH = (uint16_t*)(sm + SM_AH);
    uint16_t* AL = (uint16_t*)(sm + SM_AL);

    int tid = threadIdx.x;
    int lane = tid & 31;
    int warp = tid >> 5;
    int g = lane >> 2;
    int t = lane & 3;
    int mbase = (warp & 3) * 16;
    int nbase = (warp >> 2) * 64;

    for (int i = tid; i < 128 * 32; i += 256) {
        int j = i >> 5;
        int k4 = (i & 31) << 2;
        float4 w = __ldg((const float4*)(W + j * 128 + k4));
        uint2 h, l;
        split4(w, h, l);
        *(uint2*)(WH + j * GSTR + k4) = h;
        *(uint2*)(WL + j * GSTR + k4) = l;
    }

    for (int tile = blockIdx.x * 64; tile < nNodes; tile += gridDim.x * 64) {
        __syncthreads();

        for (int i = tid; i < 64 * 32; i += 256) {
            int r = i >> 5;
            int k4 = (i & 31) << 2;
            int row = tile + r;
            if (row >= nNodes) row = nNodes - 1;
            float4 a = __ldg((const float4*)(feat + (long)row * 128 + k4));
            uint2 h, l;
            split4(a, h, l);
            *(uint2*)(AH + r * GSTR + k4) = h;
            *(uint2*)(AL + r * GSTR + k4) = l;
        }
        __syncthreads();

        float c[8][4];
        #pragma unroll
        for (int nc = 0; nc < 8; nc++)
            #pragma unroll
            for (int i = 0; i < 4; i++) c[nc][i] = 0.f;

        #pragma unroll 1
        for (int kc = 0; kc < 8; kc++) {
            int k0 = kc * 16;
            const uint16_t* arh = AH + (mbase + g) * GSTR + k0;
            const uint16_t* arl = AL + (mbase + g) * GSTR + k0;
            uint32_t ah0 = *(const uint32_t*)(arh + t * 2);
            uint32_t ah1 = *(const uint32_t*)(arh + 8 * GSTR + t * 2);
            uint32_t ah2 = *(const uint32_t*)(arh + t * 2 + 8);
            uint32_t ah3 = *(const uint32_t*)(arh + 8 * GSTR + t * 2 + 8);
            uint32_t al0 = *(const uint32_t*)(arl + t * 2);
            uint32_t al1 = *(const uint32_t*)(arl + 8 * GSTR + t * 2);
            uint32_t al2 = *(const uint32_t*)(arl + t * 2 + 8);
            uint32_t al3 = *(const uint32_t*)(arl + 8 * GSTR + t * 2 + 8);

            #pragma unroll
            for (int nc = 0; nc < 8; nc++) {
                int j = nbase + nc * 8 + g;
                uint32_t bh0 = *(const uint32_t*)(WH + j * GSTR + k0 + t * 2);
                uint32_t bh1 = *(const uint32_t*)(WH + j * GSTR + k0 + t * 2 + 8);
                uint32_t bl0 = *(const uint32_t*)(WL + j * GSTR + k0 + t * 2);
                uint32_t bl1 = *(const uint32_t*)(WL + j * GSTR + k0 + t * 2 + 8);
                MMA_BF16(c[nc][0], c[nc][1], c[nc][2], c[nc][3],
                         ah0, ah1, ah2, ah3, bh0, bh1);
                MMA_BF16(c[nc][0], c[nc][1], c[nc][2], c[nc][3],
                         ah0, ah1, ah2, ah3, bl0, bl1);
                MMA_BF16(c[nc][0], c[nc][1], c[nc][2], c[nc][3],
                         al0, al1, al2, al3, bh0, bh1);
            }
        }

        int row0 = tile + mbase + g;
        int row1 = row0 + 8;
        #pragma unroll
        for (int nc = 0; nc < 8; nc++) {
            int n0 = nbase + nc * 8 + t * 2;
            if (row0 < nNodes)
                *(float2*)(g_fx + (long)row0 * 128 + n0) =
                    make_float2(c[nc][0], c[nc][1]);
            if (row1 < nNodes)
                *(float2*)(g_fx + (long)row1 * 128 + n0) =
                    make_float2(c[nc][2], c[nc][3]);
        }
    }
}

// ======================= gather + bias + tanh ================================
__global__ __launch_bounds__(256) void gather_tanh_kernel(
    const float* __restrict__ b, float* __restrict__ out, int nNodes) {
    int node = (blockIdx.x * 256 + threadIdx.x) >> 5;
    if (node >= nNodes) return;
    int l4 = (threadIdx.x & 31) * 4;
    float4 bv = *(const float4*)(b + l4);

    int cnt = __ldg(&g_cursor[node]);
    int ee = (cnt < CAP) ? cnt : CAP;
    const int* slots = g_slots + node * CAP;

    float4 acc = make_float4(0.f, 0.f, 0.f, 0.f);
    for (int e = 0; e < ee; e += 8) {
        #pragma unroll
        for (int u = 0; u < 8; u++) {
            int j = e + u;
            int s = __ldg(&slots[j < ee ? j : 0]);
            float4 f = *(const float4*)(g_fx + (long)s * FEATS + l4);
            if (j < ee) {
                acc.x += f.x; acc.y += f.y;
                acc.z += f.z; acc.w += f.w;
            }
        }
    }

    // overflow sweep (normally ocnt == 0: one guarded load, no loop)
    if (cnt > CAP) {
        int ocnt = __ldg(&g_ocnt);
        for (int o = 0; o < ocnt; o++) {
            int2 pr = __ldg(&g_over[o]);
            if (pr.x == node) {
                float4 f = *(const float4*)(g_fx + (long)pr.y * FEATS + l4);
                acc.x += f.x; acc.y += f.y;
                acc.z += f.z; acc.w += f.w;
            }
        }
    }

    float4 o;
    o.x = tanhf(acc.x + bv.x);
    o.y = tanhf(acc.y + bv.y);
    o.z = tanhf(acc.z + bv.z);
    o.w = tanhf(acc.w + bv.w);
    *(float4*)(out + (long)node * FEATS + l4) = o;
}

// ---------------------------------------------------------------------------
extern "C" void kernel_launch(void* const* d_in, const int* in_sizes, int n_in,
                              void* d_out, int out_size) {
    const float* feature = (const float*)d_in[0];
    const float* W       = (const float*)d_in[1];
    const float* b       = (const float*)d_in[2];
    const void*  src     = d_in[3];
    const void*  dst     = d_in[4];
    float* out = (float*)d_out;

    int nEdges = in_sizes[3];
    int nNodes = out_size / FEATS;

    static cudaStream_t s2 = nullptr;
    static cudaEvent_t eFork = nullptr, eJoin = nullptr;
    if (!s2) {
        cudaStreamCreateWithFlags(&s2, cudaStreamNonBlocking);
        cudaEventCreateWithFlags(&eFork, cudaEventDisableTiming);
        cudaEventCreateWithFlags(&eJoin, cudaEventDisableTiming);
        cudaFuncSetAttribute(gemm_mma_kernel,
                             cudaFuncAttributeMaxDynamicSharedMemorySize, GEMM_SMEM);
    }

    // fork: mma GEMM (feat @ W^T) on s2 overlaps slot-fill on stream 0
    cudaEventRecord(eFork, 0);
    cudaStreamWaitEvent(s2, eFork, 0);
    gemm_mma_kernel<<<296, 256, GEMM_SMEM, s2>>>(feature, W, nNodes);
    cudaEventRecord(eJoin, s2);

    init_kernel<<<(NN + 1023) / 1024, 1024>>>(src);
    fill_kernel<<<(nEdges / 2 + 511) / 512, 512>>>(src, dst, nEdges);

    // join, then gather + bias + tanh
    cudaStreamWaitEvent(0, eJoin, 0);
    gather_tanh_kernel<<<(nNodes * 32 + 255) / 256, 256>>>(b, out, nNodes);
}